// round 15
// baseline (speedup 1.0000x reference)
#include <cuda_runtime.h>
#include <cuda_bf16.h>
#include <cstdint>

// ---------------- problem capacities ----------------
#define NODES_MAX 50000
#define EDGE_MAX  860000

// ---------------- device scratch ----------------
__device__ float g_fs1[NODES_MAX * 256];
__device__ float g_c2 [NODES_MAX * 256];       // layer2: cols 0-127 fs2, 128-255 res2
__device__ float g_el1[NODES_MAX * 4];
__device__ float g_el2[NODES_MAX * 4];
__device__ float g_er [NODES_MAX * 4];
__device__ int   g_cnt[NODES_MAX];
__device__ int   g_cursor[NODES_MAX];
__device__ int   g_rowptr[NODES_MAX + 1];
__device__ int   g_partial[64];
__device__ int   g_csr_src[EDGE_MAX];
__device__ float g_ur1[256 * 4];
__device__ float g_ur2[256 * 4];
__device__ __nv_bfloat16 g_Ahi[NODES_MAX * 256];
__device__ __nv_bfloat16 g_Alo[NODES_MAX * 256];
__device__ __nv_bfloat16 g_B1hi[256 * 256];    // W1_src^T [n][k]
__device__ __nv_bfloat16 g_B1lo[256 * 256];
__device__ __nv_bfloat16 g_BChi[256 * 256];    // rows 0-127: W2^T, 128-255: Wres2^T
__device__ __nv_bfloat16 g_BClo[256 * 256];

// ---------------- low-level helpers ----------------
__device__ __forceinline__ uint32_t smem_u32(const void* p) {
    uint32_t a;
    asm("{ .reg .u64 t; cvta.to.shared.u64 t, %1; cvt.u32.u64 %0, t; }" : "=r"(a) : "l"(p));
    return a;
}
__device__ __forceinline__ uint32_t swz(uint32_t o) { return o ^ ((o >> 3) & 0x70); }
__device__ __forceinline__ void cp16(uint32_t dst, const void* src, int sz) {
    asm volatile("cp.async.cg.shared.global [%0], [%1], 16, %2;"
                 :: "r"(dst), "l"(src), "r"(sz) : "memory");
}
__device__ __forceinline__ void cp_commit() {
    asm volatile("cp.async.commit_group;" ::: "memory");
}
template <int N>
__device__ __forceinline__ void cp_wait() {
    asm volatile("cp.async.wait_group %0;" :: "n"(N) : "memory");
}
__device__ __forceinline__ void ldm4(uint32_t* r, uint32_t addr) {
    asm volatile("ldmatrix.sync.aligned.m8n8.x4.shared.b16 {%0,%1,%2,%3}, [%4];"
                 : "=r"(r[0]), "=r"(r[1]), "=r"(r[2]), "=r"(r[3]) : "r"(addr));
}
__device__ __forceinline__ void mma_bf16(float* d, const uint32_t* a, const uint32_t* b) {
    asm volatile(
        "mma.sync.aligned.m16n8k16.row.col.f32.bf16.bf16.f32 "
        "{%0,%1,%2,%3}, {%4,%5,%6,%7}, {%8,%9}, {%0,%1,%2,%3};"
        : "+f"(d[0]), "+f"(d[1]), "+f"(d[2]), "+f"(d[3])
        : "r"(a[0]), "r"(a[1]), "r"(a[2]), "r"(a[3]), "r"(b[0]), "r"(b[1]));
}
__device__ __forceinline__ float lrelu(float x) { return x < 0.f ? 0.2f * x : x; }

// ---------------- CSR build ----------------
__global__ void k_clear(int* cnt, int* cursor, float* el1, int n) {
    int i = blockIdx.x * blockDim.x + threadIdx.x;
    if (i < n) { cnt[i] = 0; cursor[i] = 0; }
    if (i < 4 * n) el1[i] = 0.f;
}
__global__ void k_count(const int* __restrict__ dst, int* cnt, int e_cnt) {
    int e = blockIdx.x * blockDim.x + threadIdx.x;
    if (e < e_cnt) atomicAdd(&cnt[dst[e]], 1);
}
__global__ void k_scan1(const int* __restrict__ cnt, int* rowptr, int* partial, int n) {
    __shared__ int sh[1024];
    int t = threadIdx.x;
    int idx = blockIdx.x * 1024 + t;
    int x = (idx < n) ? cnt[idx] : 0;
    sh[t] = x;
    __syncthreads();
    #pragma unroll
    for (int off = 1; off < 1024; off <<= 1) {
        int v = (t >= off) ? sh[t - off] : 0;
        __syncthreads();
        sh[t] += v;
        __syncthreads();
    }
    if (idx < n) rowptr[idx] = sh[t] - x;
    if (t == 1023) partial[blockIdx.x] = sh[1023];
}
__global__ void k_scan3(int* rowptr, const int* __restrict__ partial, int n, int e_cnt) {
    __shared__ int ws[2];
    __shared__ int s_off;
    int tid = threadIdx.x;
    int t4 = blockIdx.x >> 2;
    if (tid < 64) {
        int v = (tid < t4) ? partial[tid] : 0;
        #pragma unroll
        for (int o = 16; o; o >>= 1) v += __shfl_xor_sync(0xFFFFFFFFu, v, o);
        if ((tid & 31) == 0) ws[tid >> 5] = v;
    }
    __syncthreads();
    if (tid == 0) s_off = ws[0] + ws[1];
    __syncthreads();
    int i = blockIdx.x * 256 + tid;
    if (i < n) rowptr[i] += s_off;
    if (blockIdx.x == 0 && tid == 0) rowptr[n] = e_cnt;
}
__global__ void k_fill(const int* __restrict__ src, const int* __restrict__ dst,
                       const int* __restrict__ rowptr, int* cursor, int* csr_src, int e_cnt) {
    int e = blockIdx.x * blockDim.x + threadIdx.x;
    if (e >= e_cnt) return;
    int d = dst[e];
    int p = rowptr[d] + atomicAdd(&cursor[d], 1);
    csr_src[p] = src[e];
}

// ---------------- weight prep ----------------
__global__ void k_prep(const float* __restrict__ W1, const float* __restrict__ W2,
                       const float* __restrict__ W3,
                       const float* __restrict__ W1d, const float* __restrict__ ar1,
                       const float* __restrict__ W2d, const float* __restrict__ ar2,
                       __nv_bfloat16* b1h, __nv_bfloat16* b1l,
                       __nv_bfloat16* bch, __nv_bfloat16* bcl,
                       float* ur1, float* ur2) {
    int k = blockIdx.x;
    int n = threadIdx.x;
    if (blockIdx.y == 0) {
        float x = W1[k * 256 + n];
        __nv_bfloat16 h = __float2bfloat16(x);
        b1h[n * 256 + k] = h;
        b1l[n * 256 + k] = __float2bfloat16(x - __bfloat162float(h));
    } else if (blockIdx.y == 1) {
        if (n < 128) {
            float x = W2[k * 128 + n];
            __nv_bfloat16 h = __float2bfloat16(x);
            bch[n * 256 + k] = h;
            bcl[n * 256 + k] = __float2bfloat16(x - __bfloat162float(h));
        }
    } else if (blockIdx.y == 2) {
        if (n < 128) {
            float x = W3[k * 128 + n];
            __nv_bfloat16 h = __float2bfloat16(x);
            bch[(128 + n) * 256 + k] = h;
            bcl[(128 + n) * 256 + k] = __float2bfloat16(x - __bfloat162float(h));
        }
    } else if (blockIdx.x == 0) {
        for (int h = 0; h < 4; h++) {
            float s = 0.f;
            for (int d = 0; d < 64; d++) s += W1d[n * 256 + h * 64 + d] * ar1[h * 64 + d];
            ur1[n * 4 + h] = s;
        }
        for (int h = 0; h < 4; h++) {
            float s = 0.f;
            for (int d = 0; d < 32; d++) s += W2d[n * 128 + h * 32 + d] * ar2[h * 32 + d];
            ur2[n * 4 + h] = s;
        }
    }
}

// ---------------- conv (layer 1): warp per row, fp32 -> bf16 hi/lo ----------------
__global__ void k_conv(const float* __restrict__ A, __nv_bfloat16* __restrict__ hi,
                       __nv_bfloat16* __restrict__ lo, int N) {
    int wid = threadIdx.x >> 5, lane = threadIdx.x & 31;
    int n = blockIdx.x * 8 + wid;
    if (n >= N) return;
    const float4* arow = (const float4*)&A[(size_t)n * 256];
    float4 v0 = arow[lane * 2];
    float4 v1 = arow[lane * 2 + 1];
    float vv[8] = {v0.x, v0.y, v0.z, v0.w, v1.x, v1.y, v1.z, v1.w};
    __nv_bfloat162 hp[4], lp[4];
    #pragma unroll
    for (int j = 0; j < 4; j++) {
        __nv_bfloat16 h0 = __float2bfloat16(vv[j * 2]);
        __nv_bfloat16 h1 = __float2bfloat16(vv[j * 2 + 1]);
        hp[j] = __nv_bfloat162(h0, h1);
        lp[j] = __nv_bfloat162(__float2bfloat16(vv[j * 2] - __bfloat162float(h0)),
                               __float2bfloat16(vv[j * 2 + 1] - __bfloat162float(h1)));
    }
    *(uint4*)&hi[(size_t)n * 256 + lane * 8] = *(uint4*)hp;
    *(uint4*)&lo[(size_t)n * 256 + lane * 8] = *(uint4*)lp;
}

// ---------------- er1: warp per row, er = h . ur1 ----------------
__global__ void k_er1(const float* __restrict__ A, const float* __restrict__ ur,
                      float* __restrict__ er, int N) {
    int wid = threadIdx.x >> 5, lane = threadIdx.x & 31;
    int n = blockIdx.x * 8 + wid;
    if (n >= N) return;
    const float4* arow = (const float4*)&A[(size_t)n * 256];
    float4 v0 = arow[lane * 2];
    float4 v1 = arow[lane * 2 + 1];
    float vv[8] = {v0.x, v0.y, v0.z, v0.w, v1.x, v1.y, v1.z, v1.w};
    float4 e = make_float4(0.f, 0.f, 0.f, 0.f);
    const float4* ur4 = (const float4*)ur;
    int k = lane * 8;
    #pragma unroll
    for (int j = 0; j < 8; j++) {
        float4 u = ur4[k + j];
        e.x += vv[j] * u.x; e.y += vv[j] * u.y; e.z += vv[j] * u.z; e.w += vv[j] * u.w;
    }
    #pragma unroll
    for (int o = 16; o; o >>= 1) {
        e.x += __shfl_xor_sync(0xFFFFFFFFu, e.x, o);
        e.y += __shfl_xor_sync(0xFFFFFFFFu, e.y, o);
        e.z += __shfl_xor_sync(0xFFFFFFFFu, e.z, o);
        e.w += __shfl_xor_sync(0xFFFFFFFFu, e.w, o);
    }
    if (lane == 0) *(float4*)&er[n * 4] = e;
}

// ---------------- HMMA GEMM: tile 128x128, 512 thr, BK=64, double-buffered ----
#define STG 65536
#define GEMM_SMEM (2 * STG)

__device__ __forceinline__ void ld_stage(uint32_t sb,
    const __nv_bfloat16* Ahi, const __nv_bfloat16* Alo,
    const __nv_bfloat16* Bhi, const __nv_bfloat16* Blo,
    int bm, int bn, int kb, int M, int t) {
    #pragma unroll
    for (int i = 0; i < 2; i++) {
        int id = t + i * 512;
        int r = id >> 3, c = id & 7;
        uint32_t o = swz((uint32_t)(r * 128 + c * 16));
        int ga = bm + r;
        int sz = (ga < M) ? 16 : 0;
        if (ga >= M) ga = M - 1;
        size_t so = (size_t)ga * 256 + kb * 64 + c * 8;
        cp16(sb + o, Ahi + so, sz);
        cp16(sb + 16384 + o, Alo + so, sz);
        size_t sob = (size_t)(bn + r) * 256 + kb * 64 + c * 8;
        cp16(sb + 32768 + o, Bhi + sob, 16);
        cp16(sb + 49152 + o, Blo + sob, 16);
    }
}

__global__ __launch_bounds__(512, 1) void k_mma(
    const __nv_bfloat16* __restrict__ Ahi, const __nv_bfloat16* __restrict__ Alo,
    const __nv_bfloat16* __restrict__ Bhi, const __nv_bfloat16* __restrict__ Blo,
    float* __restrict__ C, int M,
    float* __restrict__ el, const float* __restrict__ al, int hshift, int el_cols,
    int el_store) {
    extern __shared__ char smem[];
    uint32_t sb = smem_u32(smem);
    int t = threadIdx.x;
    int lane = t & 31, wid = t >> 5;
    int wm = wid & 3, wn = wid >> 2;
    int bm = blockIdx.x * 128;
    int bn = blockIdx.y * 128;

    float acc[2][4][4];
    #pragma unroll
    for (int mt = 0; mt < 2; mt++)
        #pragma unroll
        for (int nt = 0; nt < 4; nt++)
            #pragma unroll
            for (int i = 0; i < 4; i++) acc[mt][nt][i] = 0.f;

    int a_row = wm * 32 + (lane & 15);
    int a_ch  = lane >> 4;
    int b_row = wn * 32 + (lane & 7) + ((lane >> 4) & 1) * 8;
    int b_ch  = (lane >> 3) & 1;

    ld_stage(sb, Ahi, Alo, Bhi, Blo, bm, bn, 0, M, t);
    cp_commit();

    #pragma unroll
    for (int kb = 0; kb < 4; kb++) {
        uint32_t stage = sb + (kb & 1) * STG;
        if (kb < 3) {
            ld_stage(sb + ((kb + 1) & 1) * STG, Ahi, Alo, Bhi, Blo, bm, bn, kb + 1, M, t);
            cp_commit();
            cp_wait<1>();
        } else {
            cp_wait<0>();
        }
        __syncthreads();

        #pragma unroll
        for (int ks = 0; ks < 4; ks++) {
            uint32_t ah[2][4], alr[2][4], bh[4][2], bl[4][2];
            #pragma unroll
            for (int mt = 0; mt < 2; mt++) {
                uint32_t off = swz((uint32_t)((a_row + mt * 16) * 128 + (ks * 2 + a_ch) * 16));
                ldm4(ah[mt], stage + off);
                ldm4(alr[mt], stage + 16384 + off);
            }
            #pragma unroll
            for (int p = 0; p < 2; p++) {
                uint32_t off = swz((uint32_t)((b_row + p * 16) * 128 + (ks * 2 + b_ch) * 16));
                uint32_t rh[4], rl[4];
                ldm4(rh, stage + 32768 + off);
                ldm4(rl, stage + 49152 + off);
                bh[p * 2][0] = rh[0]; bh[p * 2][1] = rh[1];
                bh[p * 2 + 1][0] = rh[2]; bh[p * 2 + 1][1] = rh[3];
                bl[p * 2][0] = rl[0]; bl[p * 2][1] = rl[1];
                bl[p * 2 + 1][0] = rl[2]; bl[p * 2 + 1][1] = rl[3];
            }
            #pragma unroll
            for (int mt = 0; mt < 2; mt++)
                #pragma unroll
                for (int nt = 0; nt < 4; nt++) {
                    mma_bf16(acc[mt][nt], ah[mt], bh[nt]);
                    mma_bf16(acc[mt][nt], alr[mt], bh[nt]);
                    mma_bf16(acc[mt][nt], ah[mt], bl[nt]);
                }
        }
        __syncthreads();
    }

    #pragma unroll
    for (int mt = 0; mt < 2; mt++) {
        int r0 = bm + wm * 32 + mt * 16 + (lane >> 2);
        #pragma unroll
        for (int nt = 0; nt < 4; nt++) {
            int c0 = bn + wn * 32 + nt * 8 + (lane & 3) * 2;
            if (r0 < M)
                *(float2*)&C[(size_t)r0 * 256 + c0] = make_float2(acc[mt][nt][0], acc[mt][nt][1]);
            if (r0 + 8 < M)
                *(float2*)&C[(size_t)(r0 + 8) * 256 + c0] = make_float2(acc[mt][nt][2], acc[mt][nt][3]);
        }
    }

    int colbase = bn + wn * 32;
    if (colbase < el_cols) {
        int h = colbase >> hshift;
        #pragma unroll
        for (int mt = 0; mt < 2; mt++) {
            float p0 = 0.f, p1 = 0.f;
            #pragma unroll
            for (int nt = 0; nt < 4; nt++) {
                int gc = colbase + nt * 8 + (lane & 3) * 2;
                float a0 = al[gc], a1 = al[gc + 1];
                p0 += acc[mt][nt][0] * a0 + acc[mt][nt][1] * a1;
                p1 += acc[mt][nt][2] * a0 + acc[mt][nt][3] * a1;
            }
            p0 += __shfl_xor_sync(0xFFFFFFFFu, p0, 1);
            p0 += __shfl_xor_sync(0xFFFFFFFFu, p0, 2);
            p1 += __shfl_xor_sync(0xFFFFFFFFu, p1, 1);
            p1 += __shfl_xor_sync(0xFFFFFFFFu, p1, 2);
            if ((lane & 3) == 0) {
                int r0 = bm + wm * 32 + mt * 16 + (lane >> 2);
                if (el_store) {
                    if (r0 < M) el[r0 * 4 + h] = p0;
                    if (r0 + 8 < M) el[(r0 + 8) * 4 + h] = p1;
                } else {
                    if (r0 < M) atomicAdd(&el[r0 * 4 + h], p0);
                    if (r0 + 8 < M) atomicAdd(&el[(r0 + 8) * 4 + h], p1);
                }
            }
        }
    }
}

// ---------------- agg layer 1 (fused softmax): + residual + ELU + bf16 + er2 ----
__global__ void k_agg1(const int* __restrict__ rowptr, const int* __restrict__ csr_src,
                       const float* __restrict__ el, const float* __restrict__ er,
                       const float* __restrict__ fs, const float* __restrict__ hin,
                       __nv_bfloat16* __restrict__ hi, __nv_bfloat16* __restrict__ lo,
                       const float* __restrict__ ur2, float* __restrict__ er2) {
    int n = blockIdx.x;
    int tid = threadIdx.x;          // 256
    int h = tid >> 6;
    int wi = tid & 63;
    int beg = rowptr[n], end = rowptr[n + 1];
    __shared__ int ss[64];
    __shared__ float sw[4][64];
    __shared__ float red[8];
    __shared__ float4 wsum[8];
    float erh = er[n * 4 + h];
    float acc = 0.f, denp = 0.f;
    for (int base = beg; base < end; base += 64) {
        int m = min(64, end - base);
        __syncthreads();
        if (tid < m) ss[tid] = csr_src[base + tid];
        __syncthreads();
        float w = 0.f;
        if (wi < m) {
            int s = ss[wi];
            w = __expf(lrelu(el[s * 4 + h] + erh));
        }
        sw[h][wi] = w;
        denp += w;
        __syncthreads();
        #pragma unroll 8
        for (int i = 0; i < m; i++)
            acc += sw[h][i] * fs[(size_t)ss[i] * 256 + tid];
    }
    #pragma unroll
    for (int o = 16; o; o >>= 1) denp += __shfl_xor_sync(0xFFFFFFFFu, denp, o);
    if ((tid & 31) == 0) red[tid >> 5] = denp;
    __syncthreads();
    float den = red[2 * h] + red[2 * h + 1];
    float v = acc / den + hin[(size_t)n * 256 + tid];
    v = v > 0.f ? v : expm1f(v);
    __nv_bfloat16 vh = __float2bfloat16(v);
    hi[(size_t)n * 256 + tid] = vh;
    lo[(size_t)n * 256 + tid] = __float2bfloat16(v - __bfloat162float(vh));
    float4 u = ((const float4*)ur2)[tid];
    float4 p = make_float4(v * u.x, v * u.y, v * u.z, v * u.w);
    #pragma unroll
    for (int o = 16; o; o >>= 1) {
        p.x += __shfl_xor_sync(0xFFFFFFFFu, p.x, o);
        p.y += __shfl_xor_sync(0xFFFFFFFFu, p.y, o);
        p.z += __shfl_xor_sync(0xFFFFFFFFu, p.z, o);
        p.w += __shfl_xor_sync(0xFFFFFFFFu, p.w, o);
    }
    if ((tid & 31) == 0) wsum[tid >> 5] = p;
    __syncthreads();
    if (tid == 0) {
        float4 s = wsum[0];
        #pragma unroll
        for (int i = 1; i < 8; i++) {
            s.x += wsum[i].x; s.y += wsum[i].y; s.z += wsum[i].z; s.w += wsum[i].w;
        }
        *(float4*)&er2[n * 4] = s;
    }
}

// ---------------- agg layer 2 (fused softmax) ----------------
__global__ void k_agg2(const int* __restrict__ rowptr, const int* __restrict__ csr_src,
                       const float* __restrict__ el, const float* __restrict__ er,
                       const float* __restrict__ c2, float* __restrict__ out) {
    int n = blockIdx.x;
    int tid = threadIdx.x;          // 128
    int h = tid >> 5;
    int wi = tid & 63;
    int whb = (tid >> 6) * 2;
    int beg = rowptr[n], end = rowptr[n + 1];
    __shared__ int ss[64];
    __shared__ float sw[4][64];
    __shared__ float red[4][2];
    __shared__ float sv[128];
    float er0 = er[n * 4 + whb], er1 = er[n * 4 + whb + 1];
    float acc = 0.f, den0 = 0.f, den1 = 0.f;
    for (int base = beg; base < end; base += 64) {
        int m = min(64, end - base);
        __syncthreads();
        if (tid < m) ss[tid] = csr_src[base + tid];
        __syncthreads();
        float w0 = 0.f, w1 = 0.f;
        if (wi < m) {
            int s = ss[wi];
            float2 ev = *(const float2*)&el[s * 4 + whb];
            w0 = __expf(lrelu(ev.x + er0));
            w1 = __expf(lrelu(ev.y + er1));
        }
        sw[whb][wi] = w0;
        sw[whb + 1][wi] = w1;
        den0 += w0; den1 += w1;
        __syncthreads();
        #pragma unroll 8
        for (int i = 0; i < m; i++)
            acc += sw[h][i] * c2[(size_t)ss[i] * 256 + tid];
    }
    #pragma unroll
    for (int o = 16; o; o >>= 1) {
        den0 += __shfl_xor_sync(0xFFFFFFFFu, den0, o);
        den1 += __shfl_xor_sync(0xFFFFFFFFu, den1, o);
    }
    if ((tid & 31) == 0) { red[tid >> 5][0] = den0; red[tid >> 5][1] = den1; }
    __syncthreads();
    float den = red[(h >> 1) * 2][h & 1] + red[(h >> 1) * 2 + 1][h & 1];
    sv[tid] = acc / den + c2[(size_t)n * 256 + 128 + tid];
    __syncthreads();
    if (tid < 32)
        out[(size_t)n * 32 + tid] =
            (sv[tid] + sv[32 + tid] + sv[64 + tid] + sv[96 + tid]) * 0.25f;
}

// ---------------- launch ----------------
extern "C" void kernel_launch(void* const* d_in, const int* in_sizes, int n_in,
                              void* d_out, int out_size) {
    const float* h      = (const float*)d_in[0];
    const int*   src    = (const int*)d_in[1];
    const int*   dst    = (const int*)d_in[2];
    const float* W1_src = (const float*)d_in[3];
    const float* W1_dst = (const float*)d_in[4];
    const float* al1    = (const float*)d_in[5];
    const float* ar1    = (const float*)d_in[6];
    const float* W2_src = (const float*)d_in[7];
    const float* W2_dst = (const float*)d_in[8];
    const float* al2    = (const float*)d_in[9];
    const float* ar2    = (const float*)d_in[10];
    const float* Wres2  = (const float*)d_in[11];
    float* out = (float*)d_out;

    int N = in_sizes[0] / 256;
    int E = in_sizes[1];

    float *fs1, *c2, *el1, *el2, *er, *ur1, *ur2;
    int *cnt, *cursor, *rowptr, *partial, *csr_src;
    __nv_bfloat16 *Ahi, *Alo, *B1h, *B1l, *BCh, *BCl;
    cudaGetSymbolAddress((void**)&fs1, g_fs1);
    cudaGetSymbolAddress((void**)&c2, g_c2);
    cudaGetSymbolAddress((void**)&el1, g_el1);
    cudaGetSymbolAddress((void**)&el2, g_el2);
    cudaGetSymbolAddress((void**)&er, g_er);
    cudaGetSymbolAddress((void**)&ur1, g_ur1);
    cudaGetSymbolAddress((void**)&ur2, g_ur2);
    cudaGetSymbolAddress((void**)&cnt, g_cnt);
    cudaGetSymbolAddress((void**)&cursor, g_cursor);
    cudaGetSymbolAddress((void**)&rowptr, g_rowptr);
    cudaGetSymbolAddress((void**)&partial, g_partial);
    cudaGetSymbolAddress((void**)&csr_src, g_csr_src);
    cudaGetSymbolAddress((void**)&Ahi, g_Ahi);
    cudaGetSymbolAddress((void**)&Alo, g_Alo);
    cudaGetSymbolAddress((void**)&B1h, g_B1hi);
    cudaGetSymbolAddress((void**)&B1l, g_B1lo);
    cudaGetSymbolAddress((void**)&BCh, g_BChi);
    cudaGetSymbolAddress((void**)&BCl, g_BClo);

    static cudaStream_t s1 = nullptr;
    static cudaEvent_t ev0 = nullptr, evP = nullptr, ev1 = nullptr;
    if (!s1) {
        cudaStreamCreateWithFlags(&s1, cudaStreamNonBlocking);
        cudaEventCreateWithFlags(&ev0, cudaEventDisableTiming);
        cudaEventCreateWithFlags(&evP, cudaEventDisableTiming);
        cudaEventCreateWithFlags(&ev1, cudaEventDisableTiming);
        cudaFuncSetAttribute(k_mma, cudaFuncAttributeMaxDynamicSharedMemorySize, GEMM_SMEM);
    }

    int gE = (E + 255) / 256;
    int gN4 = (N * 4 + 255) / 256;
    int nScanB = (N + 1023) / 1024;
    int gemmM = (N + 127) / 128;

    // ---- fork: record on capture-origin stream so s1 joins the graph ----
    cudaEventRecord(ev0, 0);

    // ---- main stream: conversion starts immediately (no dependencies) ----
    k_conv<<<(N + 7) / 8, 256>>>(h, Ahi, Alo, N);

    // ---- side stream s1: clear + prep, then CSR + er1 ----
    cudaStreamWaitEvent(s1, ev0, 0);
    k_clear<<<gN4, 256, 0, s1>>>(cnt, cursor, el1, N);
    k_prep<<<dim3(256, 4), 256, 0, s1>>>(W1_src, W2_src, Wres2, W1_dst, ar1, W2_dst, ar2,
                                         B1h, B1l, BCh, BCl, ur1, ur2);
    cudaEventRecord(evP, s1);
    k_count<<<gE, 256, 0, s1>>>(dst, cnt, E);
    k_scan1<<<nScanB, 1024, 0, s1>>>(cnt, rowptr, partial, N);
    k_scan3<<<(N + 255) / 256, 256, 0, s1>>>(rowptr, partial, N, E);
    k_fill<<<gE, 256, 0, s1>>>(src, dst, rowptr, cursor, csr_src, E);
    k_er1<<<(N + 7) / 8, 256, 0, s1>>>(h, ur1, er, N);
    cudaEventRecord(ev1, s1);

    // ---- main: GEMM1 (waits for clear+prep; conv already ordered on main) ----
    cudaStreamWaitEvent(0, evP, 0);
    k_mma<<<dim3(gemmM, 2), 512, GEMM_SMEM>>>(Ahi, Alo, B1h, B1l, fs1, N,
                                              el1, al1, 6, 256, 0);

    // join CSR + er1, then fused softmax+aggregation (writes bf16 h1 into Ahi/Alo)
    cudaStreamWaitEvent(0, ev1, 0);
    k_agg1<<<N, 256>>>(rowptr, csr_src, el1, er, fs1, h, Ahi, Alo, ur2, er);

    // ---- layer 2 ----
    k_mma<<<dim3(gemmM, 2), 512, GEMM_SMEM>>>(Ahi, Alo, BCh, BCl, c2, N,
                                              el2, al2, 5, 128, 1);
    k_agg2<<<N, 128>>>(rowptr, csr_src, el2, er, c2, out);
}

// round 16
// speedup vs baseline: 1.0356x; 1.0356x over previous
#include <cuda_runtime.h>
#include <cuda_bf16.h>
#include <cstdint>

// ---------------- problem capacities ----------------
#define NODES_MAX 50000
#define EDGE_MAX  860000

// ---------------- device scratch ----------------
__device__ float g_fs1[NODES_MAX * 256];
__device__ float g_c2 [NODES_MAX * 256];       // layer2: cols 0-127 fs2, 128-255 res2
__device__ float g_el1[NODES_MAX * 4];
__device__ float g_el2[NODES_MAX * 4];
__device__ float g_er [NODES_MAX * 4];
__device__ int   g_cnt[NODES_MAX];
__device__ int   g_cursor[NODES_MAX];
__device__ int   g_rowptr[NODES_MAX + 1];
__device__ int   g_partial[64];
__device__ int   g_csr_src[EDGE_MAX];
__device__ float g_ur1[256 * 4];
__device__ float g_ur2[256 * 4];
__device__ __nv_bfloat16 g_Ahi[NODES_MAX * 256];
__device__ __nv_bfloat16 g_Alo[NODES_MAX * 256];
__device__ __nv_bfloat16 g_B1hi[256 * 256];    // W1_src^T [n][k]
__device__ __nv_bfloat16 g_B1lo[256 * 256];
__device__ __nv_bfloat16 g_BChi[256 * 256];    // rows 0-127: W2^T, 128-255: Wres2^T
__device__ __nv_bfloat16 g_BClo[256 * 256];

// ---------------- low-level helpers ----------------
__device__ __forceinline__ uint32_t smem_u32(const void* p) {
    uint32_t a;
    asm("{ .reg .u64 t; cvta.to.shared.u64 t, %1; cvt.u32.u64 %0, t; }" : "=r"(a) : "l"(p));
    return a;
}
__device__ __forceinline__ uint32_t swz(uint32_t o) { return o ^ ((o >> 3) & 0x70); }
__device__ __forceinline__ void cp16(uint32_t dst, const void* src, int sz) {
    asm volatile("cp.async.cg.shared.global [%0], [%1], 16, %2;"
                 :: "r"(dst), "l"(src), "r"(sz) : "memory");
}
__device__ __forceinline__ void cp_commit() {
    asm volatile("cp.async.commit_group;" ::: "memory");
}
template <int N>
__device__ __forceinline__ void cp_wait() {
    asm volatile("cp.async.wait_group %0;" :: "n"(N) : "memory");
}
__device__ __forceinline__ void ldm4(uint32_t* r, uint32_t addr) {
    asm volatile("ldmatrix.sync.aligned.m8n8.x4.shared.b16 {%0,%1,%2,%3}, [%4];"
                 : "=r"(r[0]), "=r"(r[1]), "=r"(r[2]), "=r"(r[3]) : "r"(addr));
}
__device__ __forceinline__ void mma_bf16(float* d, const uint32_t* a, const uint32_t* b) {
    asm volatile(
        "mma.sync.aligned.m16n8k16.row.col.f32.bf16.bf16.f32 "
        "{%0,%1,%2,%3}, {%4,%5,%6,%7}, {%8,%9}, {%0,%1,%2,%3};"
        : "+f"(d[0]), "+f"(d[1]), "+f"(d[2]), "+f"(d[3])
        : "r"(a[0]), "r"(a[1]), "r"(a[2]), "r"(a[3]), "r"(b[0]), "r"(b[1]));
}
__device__ __forceinline__ float lrelu(float x) { return x < 0.f ? 0.2f * x : x; }

// ---------------- CSR build ----------------
__global__ void k_clear(int* cnt, int* cursor, int n) {
    int i = blockIdx.x * blockDim.x + threadIdx.x;
    if (i < n) { cnt[i] = 0; cursor[i] = 0; }
}
__global__ void k_count(const int* __restrict__ dst, int* cnt, int e_cnt) {
    int e = blockIdx.x * blockDim.x + threadIdx.x;
    if (e < e_cnt) atomicAdd(&cnt[dst[e]], 1);
}
__global__ void k_scan1(const int* __restrict__ cnt, int* rowptr, int* partial, int n) {
    __shared__ int sh[1024];
    int t = threadIdx.x;
    int idx = blockIdx.x * 1024 + t;
    int x = (idx < n) ? cnt[idx] : 0;
    sh[t] = x;
    __syncthreads();
    #pragma unroll
    for (int off = 1; off < 1024; off <<= 1) {
        int v = (t >= off) ? sh[t - off] : 0;
        __syncthreads();
        sh[t] += v;
        __syncthreads();
    }
    if (idx < n) rowptr[idx] = sh[t] - x;
    if (t == 1023) partial[blockIdx.x] = sh[1023];
}
__global__ void k_scan3(int* rowptr, const int* __restrict__ partial, int n, int e_cnt) {
    __shared__ int ws[2];
    __shared__ int s_off;
    int tid = threadIdx.x;
    int t4 = blockIdx.x >> 2;
    if (tid < 64) {
        int v = (tid < t4) ? partial[tid] : 0;
        #pragma unroll
        for (int o = 16; o; o >>= 1) v += __shfl_xor_sync(0xFFFFFFFFu, v, o);
        if ((tid & 31) == 0) ws[tid >> 5] = v;
    }
    __syncthreads();
    if (tid == 0) s_off = ws[0] + ws[1];
    __syncthreads();
    int i = blockIdx.x * 256 + tid;
    if (i < n) rowptr[i] += s_off;
    if (blockIdx.x == 0 && tid == 0) rowptr[n] = e_cnt;
}
__global__ void k_fill(const int* __restrict__ src, const int* __restrict__ dst,
                       const int* __restrict__ rowptr, int* cursor, int* csr_src, int e_cnt) {
    int e = blockIdx.x * blockDim.x + threadIdx.x;
    if (e >= e_cnt) return;
    int d = dst[e];
    int p = rowptr[d] + atomicAdd(&cursor[d], 1);
    csr_src[p] = src[e];
}

// ---------------- weight prep ----------------
__global__ void k_prep(const float* __restrict__ W1, const float* __restrict__ W2,
                       const float* __restrict__ W3,
                       const float* __restrict__ W1d, const float* __restrict__ ar1,
                       const float* __restrict__ W2d, const float* __restrict__ ar2,
                       __nv_bfloat16* b1h, __nv_bfloat16* b1l,
                       __nv_bfloat16* bch, __nv_bfloat16* bcl,
                       float* ur1, float* ur2) {
    int k = blockIdx.x;
    int n = threadIdx.x;
    if (blockIdx.y == 0) {
        float x = W1[k * 256 + n];
        __nv_bfloat16 h = __float2bfloat16(x);
        b1h[n * 256 + k] = h;
        b1l[n * 256 + k] = __float2bfloat16(x - __bfloat162float(h));
    } else if (blockIdx.y == 1) {
        if (n < 128) {
            float x = W2[k * 128 + n];
            __nv_bfloat16 h = __float2bfloat16(x);
            bch[n * 256 + k] = h;
            bcl[n * 256 + k] = __float2bfloat16(x - __bfloat162float(h));
        }
    } else if (blockIdx.y == 2) {
        if (n < 128) {
            float x = W3[k * 128 + n];
            __nv_bfloat16 h = __float2bfloat16(x);
            bch[(128 + n) * 256 + k] = h;
            bcl[(128 + n) * 256 + k] = __float2bfloat16(x - __bfloat162float(h));
        }
    } else if (blockIdx.x == 0) {
        for (int h = 0; h < 4; h++) {
            float s = 0.f;
            for (int d = 0; d < 64; d++) s += W1d[n * 256 + h * 64 + d] * ar1[h * 64 + d];
            ur1[n * 4 + h] = s;
        }
        for (int h = 0; h < 4; h++) {
            float s = 0.f;
            for (int d = 0; d < 32; d++) s += W2d[n * 128 + h * 32 + d] * ar2[h * 32 + d];
            ur2[n * 4 + h] = s;
        }
    }
}

// ---------------- convA + er (layer 1): warp per row ----------------
__global__ void k_convA_er(const float* __restrict__ A, __nv_bfloat16* __restrict__ hi,
                           __nv_bfloat16* __restrict__ lo, const float* __restrict__ ur,
                           float* __restrict__ er, int N) {
    int wid = threadIdx.x >> 5, lane = threadIdx.x & 31;
    int n = blockIdx.x * 8 + wid;
    if (n >= N) return;
    const float4* arow = (const float4*)&A[(size_t)n * 256];
    float4 v0 = arow[lane * 2];
    float4 v1 = arow[lane * 2 + 1];
    float vv[8] = {v0.x, v0.y, v0.z, v0.w, v1.x, v1.y, v1.z, v1.w};
    __nv_bfloat162 hp[4], lp[4];
    #pragma unroll
    for (int j = 0; j < 4; j++) {
        __nv_bfloat16 h0 = __float2bfloat16(vv[j * 2]);
        __nv_bfloat16 h1 = __float2bfloat16(vv[j * 2 + 1]);
        hp[j] = __nv_bfloat162(h0, h1);
        lp[j] = __nv_bfloat162(__float2bfloat16(vv[j * 2] - __bfloat162float(h0)),
                               __float2bfloat16(vv[j * 2 + 1] - __bfloat162float(h1)));
    }
    *(uint4*)&hi[(size_t)n * 256 + lane * 8] = *(uint4*)hp;
    *(uint4*)&lo[(size_t)n * 256 + lane * 8] = *(uint4*)lp;
    float4 e = make_float4(0.f, 0.f, 0.f, 0.f);
    const float4* ur4 = (const float4*)ur;
    int k = lane * 8;
    #pragma unroll
    for (int j = 0; j < 8; j++) {
        float4 u = ur4[k + j];
        e.x += vv[j] * u.x; e.y += vv[j] * u.y; e.z += vv[j] * u.z; e.w += vv[j] * u.w;
    }
    #pragma unroll
    for (int o = 16; o; o >>= 1) {
        e.x += __shfl_xor_sync(0xFFFFFFFFu, e.x, o);
        e.y += __shfl_xor_sync(0xFFFFFFFFu, e.y, o);
        e.z += __shfl_xor_sync(0xFFFFFFFFu, e.z, o);
        e.w += __shfl_xor_sync(0xFFFFFFFFu, e.w, o);
    }
    if (lane == 0) *(float4*)&er[n * 4] = e;
}

// ---------------- HMMA GEMM: tile 128x128, 512 thr, BK=64, double-buffered ----
// el epilogue: el_pair=1 -> heads span 2 warps (layer 1), combine in smem, plain store.
//              el_pair=0 -> one warp per head (layer 2), direct store.
#define STG 65536
#define GEMM_SMEM (2 * STG)

__device__ __forceinline__ void ld_stage(uint32_t sb,
    const __nv_bfloat16* Ahi, const __nv_bfloat16* Alo,
    const __nv_bfloat16* Bhi, const __nv_bfloat16* Blo,
    int bm, int bn, int kb, int M, int t) {
    #pragma unroll
    for (int i = 0; i < 2; i++) {
        int id = t + i * 512;
        int r = id >> 3, c = id & 7;
        uint32_t o = swz((uint32_t)(r * 128 + c * 16));
        int ga = bm + r;
        int sz = (ga < M) ? 16 : 0;
        if (ga >= M) ga = M - 1;
        size_t so = (size_t)ga * 256 + kb * 64 + c * 8;
        cp16(sb + o, Ahi + so, sz);
        cp16(sb + 16384 + o, Alo + so, sz);
        size_t sob = (size_t)(bn + r) * 256 + kb * 64 + c * 8;
        cp16(sb + 32768 + o, Bhi + sob, 16);
        cp16(sb + 49152 + o, Blo + sob, 16);
    }
}

__global__ __launch_bounds__(512, 1) void k_mma(
    const __nv_bfloat16* __restrict__ Ahi, const __nv_bfloat16* __restrict__ Alo,
    const __nv_bfloat16* __restrict__ Bhi, const __nv_bfloat16* __restrict__ Blo,
    float* __restrict__ C, int M,
    float* __restrict__ el, const float* __restrict__ al, int hshift, int el_cols,
    int el_pair) {
    extern __shared__ char smem[];
    __shared__ float elbuf[4][128];
    uint32_t sb = smem_u32(smem);
    int t = threadIdx.x;
    int lane = t & 31, wid = t >> 5;
    int wm = wid & 3, wn = wid >> 2;
    int bm = blockIdx.x * 128;
    int bn = blockIdx.y * 128;

    float acc[2][4][4];
    #pragma unroll
    for (int mt = 0; mt < 2; mt++)
        #pragma unroll
        for (int nt = 0; nt < 4; nt++)
            #pragma unroll
            for (int i = 0; i < 4; i++) acc[mt][nt][i] = 0.f;

    int a_row = wm * 32 + (lane & 15);
    int a_ch  = lane >> 4;
    int b_row = wn * 32 + (lane & 7) + ((lane >> 4) & 1) * 8;
    int b_ch  = (lane >> 3) & 1;

    ld_stage(sb, Ahi, Alo, Bhi, Blo, bm, bn, 0, M, t);
    cp_commit();

    #pragma unroll
    for (int kb = 0; kb < 4; kb++) {
        uint32_t stage = sb + (kb & 1) * STG;
        if (kb < 3) {
            ld_stage(sb + ((kb + 1) & 1) * STG, Ahi, Alo, Bhi, Blo, bm, bn, kb + 1, M, t);
            cp_commit();
            cp_wait<1>();
        } else {
            cp_wait<0>();
        }
        __syncthreads();

        #pragma unroll
        for (int ks = 0; ks < 4; ks++) {
            uint32_t ah[2][4], alr[2][4], bh[4][2], bl[4][2];
            #pragma unroll
            for (int mt = 0; mt < 2; mt++) {
                uint32_t off = swz((uint32_t)((a_row + mt * 16) * 128 + (ks * 2 + a_ch) * 16));
                ldm4(ah[mt], stage + off);
                ldm4(alr[mt], stage + 16384 + off);
            }
            #pragma unroll
            for (int p = 0; p < 2; p++) {
                uint32_t off = swz((uint32_t)((b_row + p * 16) * 128 + (ks * 2 + b_ch) * 16));
                uint32_t rh[4], rl[4];
                ldm4(rh, stage + 32768 + off);
                ldm4(rl, stage + 49152 + off);
                bh[p * 2][0] = rh[0]; bh[p * 2][1] = rh[1];
                bh[p * 2 + 1][0] = rh[2]; bh[p * 2 + 1][1] = rh[3];
                bl[p * 2][0] = rl[0]; bl[p * 2][1] = rl[1];
                bl[p * 2 + 1][0] = rl[2]; bl[p * 2 + 1][1] = rl[3];
            }
            #pragma unroll
            for (int mt = 0; mt < 2; mt++)
                #pragma unroll
                for (int nt = 0; nt < 4; nt++) {
                    mma_bf16(acc[mt][nt], ah[mt], bh[nt]);
                    mma_bf16(acc[mt][nt], alr[mt], bh[nt]);
                    mma_bf16(acc[mt][nt], ah[mt], bl[nt]);
                }
        }
        __syncthreads();
    }

    #pragma unroll
    for (int mt = 0; mt < 2; mt++) {
        int r0 = bm + wm * 32 + mt * 16 + (lane >> 2);
        #pragma unroll
        for (int nt = 0; nt < 4; nt++) {
            int c0 = bn + wn * 32 + nt * 8 + (lane & 3) * 2;
            if (r0 < M)
                *(float2*)&C[(size_t)r0 * 256 + c0] = make_float2(acc[mt][nt][0], acc[mt][nt][1]);
            if (r0 + 8 < M)
                *(float2*)&C[(size_t)(r0 + 8) * 256 + c0] = make_float2(acc[mt][nt][2], acc[mt][nt][3]);
        }
    }

    int colbase = bn + wn * 32;
    if (colbase < el_cols) {
        #pragma unroll
        for (int mt = 0; mt < 2; mt++) {
            float p0 = 0.f, p1 = 0.f;
            #pragma unroll
            for (int nt = 0; nt < 4; nt++) {
                int gc = colbase + nt * 8 + (lane & 3) * 2;
                float a0 = al[gc], a1 = al[gc + 1];
                p0 += acc[mt][nt][0] * a0 + acc[mt][nt][1] * a1;
                p1 += acc[mt][nt][2] * a0 + acc[mt][nt][3] * a1;
            }
            p0 += __shfl_xor_sync(0xFFFFFFFFu, p0, 1);
            p0 += __shfl_xor_sync(0xFFFFFFFFu, p0, 2);
            p1 += __shfl_xor_sync(0xFFFFFFFFu, p1, 1);
            p1 += __shfl_xor_sync(0xFFFFFFFFu, p1, 2);
            if ((lane & 3) == 0) {
                int rl0 = wm * 32 + mt * 16 + (lane >> 2);
                if (el_pair) {
                    elbuf[wn][rl0] = p0;
                    elbuf[wn][rl0 + 8] = p1;
                } else {
                    int h = colbase >> hshift;
                    if (bm + rl0 < M) el[(bm + rl0) * 4 + h] = p0;
                    if (bm + rl0 + 8 < M) el[(bm + rl0 + 8) * 4 + h] = p1;
                }
            }
        }
    }
    if (el_pair) {
        __syncthreads();
        if (t < 256) {
            int r = t & 127;
            int pr = t >> 7;                 // 0..1 : warp-pair index
            int gr = bm + r;
            if (gr < M) {
                float v = elbuf[pr * 2][r] + elbuf[pr * 2 + 1][r];
                int h = (bn >> 6) + pr;      // heads {0,1} for bn=0, {2,3} for bn=128
                el[gr * 4 + h] = v;
            }
        }
    }
}

// ---------------- agg layer 1 (fused softmax): + residual + ELU + bf16 + er2 ----
__global__ void k_agg1(const int* __restrict__ rowptr, const int* __restrict__ csr_src,
                       const float* __restrict__ el, const float* __restrict__ er,
                       const float* __restrict__ fs, const float* __restrict__ hin,
                       __nv_bfloat16* __restrict__ hi, __nv_bfloat16* __restrict__ lo,
                       const float* __restrict__ ur2, float* __restrict__ er2) {
    int n = blockIdx.x;
    int tid = threadIdx.x;          // 256
    int h = tid >> 6;
    int wi = tid & 63;
    int beg = rowptr[n], end = rowptr[n + 1];
    __shared__ int ss[64];
    __shared__ float sw[4][64];
    __shared__ float red[8];
    __shared__ float4 wsum[8];
    float erh = er[n * 4 + h];
    float acc = 0.f, denp = 0.f;
    for (int base = beg; base < end; base += 64) {
        int m = min(64, end - base);
        __syncthreads();
        if (tid < m) ss[tid] = csr_src[base + tid];
        __syncthreads();
        float w = 0.f;
        if (wi < m) {
            int s = ss[wi];
            w = __expf(lrelu(el[s * 4 + h] + erh));
        }
        sw[h][wi] = w;
        denp += w;
        __syncthreads();
        #pragma unroll 8
        for (int i = 0; i < m; i++)
            acc += sw[h][i] * fs[(size_t)ss[i] * 256 + tid];
    }
    #pragma unroll
    for (int o = 16; o; o >>= 1) denp += __shfl_xor_sync(0xFFFFFFFFu, denp, o);
    if ((tid & 31) == 0) red[tid >> 5] = denp;
    __syncthreads();
    float den = red[2 * h] + red[2 * h + 1];
    float v = acc / den + hin[(size_t)n * 256 + tid];
    v = v > 0.f ? v : expm1f(v);
    __nv_bfloat16 vh = __float2bfloat16(v);
    hi[(size_t)n * 256 + tid] = vh;
    lo[(size_t)n * 256 + tid] = __float2bfloat16(v - __bfloat162float(vh));
    float4 u = ((const float4*)ur2)[tid];
    float4 p = make_float4(v * u.x, v * u.y, v * u.z, v * u.w);
    #pragma unroll
    for (int o = 16; o; o >>= 1) {
        p.x += __shfl_xor_sync(0xFFFFFFFFu, p.x, o);
        p.y += __shfl_xor_sync(0xFFFFFFFFu, p.y, o);
        p.z += __shfl_xor_sync(0xFFFFFFFFu, p.z, o);
        p.w += __shfl_xor_sync(0xFFFFFFFFu, p.w, o);
    }
    if ((tid & 31) == 0) wsum[tid >> 5] = p;
    __syncthreads();
    if (tid == 0) {
        float4 s = wsum[0];
        #pragma unroll
        for (int i = 1; i < 8; i++) {
            s.x += wsum[i].x; s.y += wsum[i].y; s.z += wsum[i].z; s.w += wsum[i].w;
        }
        *(float4*)&er2[n * 4] = s;
    }
}

// ---------------- agg layer 2 (fused softmax) ----------------
__global__ void k_agg2(const int* __restrict__ rowptr, const int* __restrict__ csr_src,
                       const float* __restrict__ el, const float* __restrict__ er,
                       const float* __restrict__ c2, float* __restrict__ out) {
    int n = blockIdx.x;
    int tid = threadIdx.x;          // 128
    int h = tid >> 5;
    int wi = tid & 63;
    int whb = (tid >> 6) * 2;
    int beg = rowptr[n], end = rowptr[n + 1];
    __shared__ int ss[64];
    __shared__ float sw[4][64];
    __shared__ float red[4][2];
    __shared__ float sv[128];
    float er0 = er[n * 4 + whb], er1 = er[n * 4 + whb + 1];
    float acc = 0.f, den0 = 0.f, den1 = 0.f;
    for (int base = beg; base < end; base += 64) {
        int m = min(64, end - base);
        __syncthreads();
        if (tid < m) ss[tid] = csr_src[base + tid];
        __syncthreads();
        float w0 = 0.f, w1 = 0.f;
        if (wi < m) {
            int s = ss[wi];
            float2 ev = *(const float2*)&el[s * 4 + whb];
            w0 = __expf(lrelu(ev.x + er0));
            w1 = __expf(lrelu(ev.y + er1));
        }
        sw[whb][wi] = w0;
        sw[whb + 1][wi] = w1;
        den0 += w0; den1 += w1;
        __syncthreads();
        #pragma unroll 8
        for (int i = 0; i < m; i++)
            acc += sw[h][i] * c2[(size_t)ss[i] * 256 + tid];
    }
    #pragma unroll
    for (int o = 16; o; o >>= 1) {
        den0 += __shfl_xor_sync(0xFFFFFFFFu, den0, o);
        den1 += __shfl_xor_sync(0xFFFFFFFFu, den1, o);
    }
    if ((tid & 31) == 0) { red[tid >> 5][0] = den0; red[tid >> 5][1] = den1; }
    __syncthreads();
    float den = red[(h >> 1) * 2][h & 1] + red[(h >> 1) * 2 + 1][h & 1];
    sv[tid] = acc / den + c2[(size_t)n * 256 + 128 + tid];
    __syncthreads();
    if (tid < 32)
        out[(size_t)n * 32 + tid] =
            (sv[tid] + sv[32 + tid] + sv[64 + tid] + sv[96 + tid]) * 0.25f;
}

// ---------------- launch ----------------
extern "C" void kernel_launch(void* const* d_in, const int* in_sizes, int n_in,
                              void* d_out, int out_size) {
    const float* h      = (const float*)d_in[0];
    const int*   src    = (const int*)d_in[1];
    const int*   dst    = (const int*)d_in[2];
    const float* W1_src = (const float*)d_in[3];
    const float* W1_dst = (const float*)d_in[4];
    const float* al1    = (const float*)d_in[5];
    const float* ar1    = (const float*)d_in[6];
    const float* W2_src = (const float*)d_in[7];
    const float* W2_dst = (const float*)d_in[8];
    const float* al2    = (const float*)d_in[9];
    const float* ar2    = (const float*)d_in[10];
    const float* Wres2  = (const float*)d_in[11];
    float* out = (float*)d_out;

    int N = in_sizes[0] / 256;
    int E = in_sizes[1];

    float *fs1, *c2, *el1, *el2, *er, *ur1, *ur2;
    int *cnt, *cursor, *rowptr, *partial, *csr_src;
    __nv_bfloat16 *Ahi, *Alo, *B1h, *B1l, *BCh, *BCl;
    cudaGetSymbolAddress((void**)&fs1, g_fs1);
    cudaGetSymbolAddress((void**)&c2, g_c2);
    cudaGetSymbolAddress((void**)&el1, g_el1);
    cudaGetSymbolAddress((void**)&el2, g_el2);
    cudaGetSymbolAddress((void**)&er, g_er);
    cudaGetSymbolAddress((void**)&ur1, g_ur1);
    cudaGetSymbolAddress((void**)&ur2, g_ur2);
    cudaGetSymbolAddress((void**)&cnt, g_cnt);
    cudaGetSymbolAddress((void**)&cursor, g_cursor);
    cudaGetSymbolAddress((void**)&rowptr, g_rowptr);
    cudaGetSymbolAddress((void**)&partial, g_partial);
    cudaGetSymbolAddress((void**)&csr_src, g_csr_src);
    cudaGetSymbolAddress((void**)&Ahi, g_Ahi);
    cudaGetSymbolAddress((void**)&Alo, g_Alo);
    cudaGetSymbolAddress((void**)&B1h, g_B1hi);
    cudaGetSymbolAddress((void**)&B1l, g_B1lo);
    cudaGetSymbolAddress((void**)&BCh, g_BChi);
    cudaGetSymbolAddress((void**)&BCl, g_BClo);

    static cudaStream_t s1 = nullptr;
    static cudaEvent_t ev0 = nullptr, ev1 = nullptr;
    if (!s1) {
        cudaStreamCreateWithFlags(&s1, cudaStreamNonBlocking);
        cudaEventCreateWithFlags(&ev0, cudaEventDisableTiming);
        cudaEventCreateWithFlags(&ev1, cudaEventDisableTiming);
        cudaFuncSetAttribute(k_mma, cudaFuncAttributeMaxDynamicSharedMemorySize, GEMM_SMEM);
    }

    int gE = (E + 255) / 256;
    int gN = (N + 255) / 256;
    int nScanB = (N + 1023) / 1024;
    int gemmM = (N + 127) / 128;

    // clear (cnt/cursor for CSR; el no longer needs init)
    k_clear<<<gN, 256>>>(cnt, cursor, N);
    cudaEventRecord(ev0, 0);

    // ---- side stream s1: CSR build ----
    cudaStreamWaitEvent(s1, ev0, 0);
    k_count<<<gE, 256, 0, s1>>>(dst, cnt, E);
    k_scan1<<<nScanB, 1024, 0, s1>>>(cnt, rowptr, partial, N);
    k_scan3<<<(N + 255) / 256, 256, 0, s1>>>(rowptr, partial, N, E);
    k_fill<<<gE, 256, 0, s1>>>(src, dst, rowptr, cursor, csr_src, E);
    cudaEventRecord(ev1, s1);

    // ---- main stream: weight prep + convert + GEMM L1 ----
    k_prep<<<dim3(256, 4), 256>>>(W1_src, W2_src, Wres2, W1_dst, ar1, W2_dst, ar2,
                                  B1h, B1l, BCh, BCl, ur1, ur2);
    k_convA_er<<<(N + 7) / 8, 256>>>(h, Ahi, Alo, ur1, er, N);
    k_mma<<<dim3(gemmM, 2), 512, GEMM_SMEM>>>(Ahi, Alo, B1h, B1l, fs1, N,
                                              el1, al1, 6, 256, 1);

    // join CSR branch, then fused softmax+aggregation (writes bf16 h1 into Ahi/Alo)
    cudaStreamWaitEvent(0, ev1, 0);
    k_agg1<<<N, 256>>>(rowptr, csr_src, el1, er, fs1, h, Ahi, Alo, ur2, er);

    // ---- layer 2 ----
    k_mma<<<dim3(gemmM, 2), 512, GEMM_SMEM>>>(Ahi, Alo, BCh, BCl, c2, N,
                                              el2, al2, 5, 128, 0);
    k_agg2<<<N, 128>>>(rowptr, csr_src, el2, er, c2, out);
}

// round 17
// speedup vs baseline: 1.2114x; 1.1698x over previous
#include <cuda_runtime.h>
#include <cuda_bf16.h>
#include <cstdint>

// ---------------- problem capacities ----------------
#define NODES_MAX 50000
#define EDGE_MAX  860000

// ---------------- device scratch ----------------
__device__ float g_fs1[NODES_MAX * 256];
__device__ float g_c2 [NODES_MAX * 256];       // layer2: cols 0-127 fs2, 128-255 res2
__device__ float g_el1[NODES_MAX * 4];
__device__ float g_el2[NODES_MAX * 4];
__device__ float g_er [NODES_MAX * 4];
__device__ int   g_cnt[NODES_MAX];
__device__ int   g_cursor[NODES_MAX];
__device__ int   g_rowptr[NODES_MAX + 1];
__device__ int   g_partial[64];
__device__ int   g_csr_src[EDGE_MAX];
__device__ float g_ur1[256 * 4];
__device__ float g_ur2[256 * 4];
__device__ __nv_bfloat16 g_Ahi[NODES_MAX * 256];
__device__ __nv_bfloat16 g_Alo[NODES_MAX * 256];
__device__ __nv_bfloat16 g_B1hi[256 * 256];    // W1_src^T [n][k]
__device__ __nv_bfloat16 g_B1lo[256 * 256];
__device__ __nv_bfloat16 g_BChi[256 * 256];    // rows 0-127: W2^T, 128-255: Wres2^T
__device__ __nv_bfloat16 g_BClo[256 * 256];

// ---------------- low-level helpers ----------------
__device__ __forceinline__ uint32_t smem_u32(const void* p) {
    uint32_t a;
    asm("{ .reg .u64 t; cvta.to.shared.u64 t, %1; cvt.u32.u64 %0, t; }" : "=r"(a) : "l"(p));
    return a;
}
__device__ __forceinline__ uint32_t swz(uint32_t o) { return o ^ ((o >> 3) & 0x70); }
__device__ __forceinline__ void cp16(uint32_t dst, const void* src, int sz) {
    asm volatile("cp.async.cg.shared.global [%0], [%1], 16, %2;"
                 :: "r"(dst), "l"(src), "r"(sz) : "memory");
}
__device__ __forceinline__ void cp_commit() {
    asm volatile("cp.async.commit_group;" ::: "memory");
}
template <int N>
__device__ __forceinline__ void cp_wait() {
    asm volatile("cp.async.wait_group %0;" :: "n"(N) : "memory");
}
__device__ __forceinline__ void ldm4(uint32_t* r, uint32_t addr) {
    asm volatile("ldmatrix.sync.aligned.m8n8.x4.shared.b16 {%0,%1,%2,%3}, [%4];"
                 : "=r"(r[0]), "=r"(r[1]), "=r"(r[2]), "=r"(r[3]) : "r"(addr));
}
__device__ __forceinline__ void mma_bf16(float* d, const uint32_t* a, const uint32_t* b) {
    asm volatile(
        "mma.sync.aligned.m16n8k16.row.col.f32.bf16.bf16.f32 "
        "{%0,%1,%2,%3}, {%4,%5,%6,%7}, {%8,%9}, {%0,%1,%2,%3};"
        : "+f"(d[0]), "+f"(d[1]), "+f"(d[2]), "+f"(d[3])
        : "r"(a[0]), "r"(a[1]), "r"(a[2]), "r"(a[3]), "r"(b[0]), "r"(b[1]));
}
__device__ __forceinline__ float lrelu(float x) { return x < 0.f ? 0.2f * x : x; }

// ---------------- CSR build ----------------
__global__ void k_clear(int* cnt, int* cursor, int n) {
    int i = blockIdx.x * blockDim.x + threadIdx.x;
    if (i < n) { cnt[i] = 0; cursor[i] = 0; }
}
__global__ void k_count(const int* __restrict__ dst, int* cnt, int e_cnt) {
    int e = blockIdx.x * blockDim.x + threadIdx.x;
    if (e < e_cnt) atomicAdd(&cnt[dst[e]], 1);
}
__global__ void k_scan1(const int* __restrict__ cnt, int* rowptr, int* partial, int n) {
    __shared__ int sh[1024];
    int t = threadIdx.x;
    int idx = blockIdx.x * 1024 + t;
    int x = (idx < n) ? cnt[idx] : 0;
    sh[t] = x;
    __syncthreads();
    #pragma unroll
    for (int off = 1; off < 1024; off <<= 1) {
        int v = (t >= off) ? sh[t - off] : 0;
        __syncthreads();
        sh[t] += v;
        __syncthreads();
    }
    if (idx < n) rowptr[idx] = sh[t] - x;
    if (t == 1023) partial[blockIdx.x] = sh[1023];
}
__global__ void k_scan3(int* rowptr, const int* __restrict__ partial, int n, int e_cnt) {
    __shared__ int ws[2];
    __shared__ int s_off;
    int tid = threadIdx.x;
    int t4 = blockIdx.x >> 2;
    if (tid < 64) {
        int v = (tid < t4) ? partial[tid] : 0;
        #pragma unroll
        for (int o = 16; o; o >>= 1) v += __shfl_xor_sync(0xFFFFFFFFu, v, o);
        if ((tid & 31) == 0) ws[tid >> 5] = v;
    }
    __syncthreads();
    if (tid == 0) s_off = ws[0] + ws[1];
    __syncthreads();
    int i = blockIdx.x * 256 + tid;
    if (i < n) rowptr[i] += s_off;
    if (blockIdx.x == 0 && tid == 0) rowptr[n] = e_cnt;
}
__global__ void k_fill(const int* __restrict__ src, const int* __restrict__ dst,
                       const int* __restrict__ rowptr, int* cursor, int* csr_src, int e_cnt) {
    int e = blockIdx.x * blockDim.x + threadIdx.x;
    if (e >= e_cnt) return;
    int d = dst[e];
    int p = rowptr[d] + atomicAdd(&cursor[d], 1);
    csr_src[p] = src[e];
}

// ---------------- weight prep ----------------
__global__ void k_prep(const float* __restrict__ W1, const float* __restrict__ W2,
                       const float* __restrict__ W3,
                       const float* __restrict__ W1d, const float* __restrict__ ar1,
                       const float* __restrict__ W2d, const float* __restrict__ ar2,
                       __nv_bfloat16* b1h, __nv_bfloat16* b1l,
                       __nv_bfloat16* bch, __nv_bfloat16* bcl,
                       float* ur1, float* ur2) {
    int k = blockIdx.x;
    int n = threadIdx.x;
    if (blockIdx.y == 0) {
        float x = W1[k * 256 + n];
        __nv_bfloat16 h = __float2bfloat16(x);
        b1h[n * 256 + k] = h;
        b1l[n * 256 + k] = __float2bfloat16(x - __bfloat162float(h));
    } else if (blockIdx.y == 1) {
        if (n < 128) {
            float x = W2[k * 128 + n];
            __nv_bfloat16 h = __float2bfloat16(x);
            bch[n * 256 + k] = h;
            bcl[n * 256 + k] = __float2bfloat16(x - __bfloat162float(h));
        }
    } else if (blockIdx.y == 2) {
        if (n < 128) {
            float x = W3[k * 128 + n];
            __nv_bfloat16 h = __float2bfloat16(x);
            bch[(128 + n) * 256 + k] = h;
            bcl[(128 + n) * 256 + k] = __float2bfloat16(x - __bfloat162float(h));
        }
    } else if (blockIdx.x == 0) {
        for (int h = 0; h < 4; h++) {
            float s = 0.f;
            for (int d = 0; d < 64; d++) s += W1d[n * 256 + h * 64 + d] * ar1[h * 64 + d];
            ur1[n * 4 + h] = s;
        }
        for (int h = 0; h < 4; h++) {
            float s = 0.f;
            for (int d = 0; d < 32; d++) s += W2d[n * 128 + h * 32 + d] * ar2[h * 32 + d];
            ur2[n * 4 + h] = s;
        }
    }
}

// ---------------- convA + er (layer 1): warp per row ----------------
__global__ void k_convA_er(const float* __restrict__ A, __nv_bfloat16* __restrict__ hi,
                           __nv_bfloat16* __restrict__ lo, const float* __restrict__ ur,
                           float* __restrict__ er, int N) {
    int wid = threadIdx.x >> 5, lane = threadIdx.x & 31;
    int n = blockIdx.x * 8 + wid;
    if (n >= N) return;
    const float4* arow = (const float4*)&A[(size_t)n * 256];
    float4 v0 = arow[lane * 2];
    float4 v1 = arow[lane * 2 + 1];
    float vv[8] = {v0.x, v0.y, v0.z, v0.w, v1.x, v1.y, v1.z, v1.w};
    __nv_bfloat162 hp[4], lp[4];
    #pragma unroll
    for (int j = 0; j < 4; j++) {
        __nv_bfloat16 h0 = __float2bfloat16(vv[j * 2]);
        __nv_bfloat16 h1 = __float2bfloat16(vv[j * 2 + 1]);
        hp[j] = __nv_bfloat162(h0, h1);
        lp[j] = __nv_bfloat162(__float2bfloat16(vv[j * 2] - __bfloat162float(h0)),
                               __float2bfloat16(vv[j * 2 + 1] - __bfloat162float(h1)));
    }
    *(uint4*)&hi[(size_t)n * 256 + lane * 8] = *(uint4*)hp;
    *(uint4*)&lo[(size_t)n * 256 + lane * 8] = *(uint4*)lp;
    float4 e = make_float4(0.f, 0.f, 0.f, 0.f);
    const float4* ur4 = (const float4*)ur;
    int k = lane * 8;
    #pragma unroll
    for (int j = 0; j < 8; j++) {
        float4 u = ur4[k + j];
        e.x += vv[j] * u.x; e.y += vv[j] * u.y; e.z += vv[j] * u.z; e.w += vv[j] * u.w;
    }
    #pragma unroll
    for (int o = 16; o; o >>= 1) {
        e.x += __shfl_xor_sync(0xFFFFFFFFu, e.x, o);
        e.y += __shfl_xor_sync(0xFFFFFFFFu, e.y, o);
        e.z += __shfl_xor_sync(0xFFFFFFFFu, e.z, o);
        e.w += __shfl_xor_sync(0xFFFFFFFFu, e.w, o);
    }
    if (lane == 0) *(float4*)&er[n * 4] = e;
}

// ---------------- HMMA GEMM: tile 128x128, 512 thr, BK=64, double-buffered ----
// el epilogue: el_pair=1 -> smem pair-combine + plain store (layer 1);
//              el_pair=0 -> one warp per head, direct store (layer 2).
#define STG 65536
#define GEMM_SMEM (2 * STG)

__device__ __forceinline__ void ld_stage(uint32_t sb,
    const __nv_bfloat16* Ahi, const __nv_bfloat16* Alo,
    const __nv_bfloat16* Bhi, const __nv_bfloat16* Blo,
    int bm, int bn, int kb, int M, int t) {
    #pragma unroll
    for (int i = 0; i < 2; i++) {
        int id = t + i * 512;
        int r = id >> 3, c = id & 7;
        uint32_t o = swz((uint32_t)(r * 128 + c * 16));
        int ga = bm + r;
        int sz = (ga < M) ? 16 : 0;
        if (ga >= M) ga = M - 1;
        size_t so = (size_t)ga * 256 + kb * 64 + c * 8;
        cp16(sb + o, Ahi + so, sz);
        cp16(sb + 16384 + o, Alo + so, sz);
        size_t sob = (size_t)(bn + r) * 256 + kb * 64 + c * 8;
        cp16(sb + 32768 + o, Bhi + sob, 16);
        cp16(sb + 49152 + o, Blo + sob, 16);
    }
}

__global__ __launch_bounds__(512, 1) void k_mma(
    const __nv_bfloat16* __restrict__ Ahi, const __nv_bfloat16* __restrict__ Alo,
    const __nv_bfloat16* __restrict__ Bhi, const __nv_bfloat16* __restrict__ Blo,
    float* __restrict__ C, int M,
    float* __restrict__ el, const float* __restrict__ al, int hshift, int el_cols,
    int el_pair) {
    extern __shared__ char smem[];
    __shared__ float elbuf[4][128];
    uint32_t sb = smem_u32(smem);
    int t = threadIdx.x;
    int lane = t & 31, wid = t >> 5;
    int wm = wid & 3, wn = wid >> 2;
    int bm = blockIdx.x * 128;
    int bn = blockIdx.y * 128;

    float acc[2][4][4];
    #pragma unroll
    for (int mt = 0; mt < 2; mt++)
        #pragma unroll
        for (int nt = 0; nt < 4; nt++)
            #pragma unroll
            for (int i = 0; i < 4; i++) acc[mt][nt][i] = 0.f;

    int a_row = wm * 32 + (lane & 15);
    int a_ch  = lane >> 4;
    int b_row = wn * 32 + (lane & 7) + ((lane >> 4) & 1) * 8;
    int b_ch  = (lane >> 3) & 1;

    ld_stage(sb, Ahi, Alo, Bhi, Blo, bm, bn, 0, M, t);
    cp_commit();

    #pragma unroll
    for (int kb = 0; kb < 4; kb++) {
        uint32_t stage = sb + (kb & 1) * STG;
        if (kb < 3) {
            ld_stage(sb + ((kb + 1) & 1) * STG, Ahi, Alo, Bhi, Blo, bm, bn, kb + 1, M, t);
            cp_commit();
            cp_wait<1>();
        } else {
            cp_wait<0>();
        }
        __syncthreads();

        #pragma unroll
        for (int ks = 0; ks < 4; ks++) {
            uint32_t ah[2][4], alr[2][4], bh[4][2], bl[4][2];
            #pragma unroll
            for (int mt = 0; mt < 2; mt++) {
                uint32_t off = swz((uint32_t)((a_row + mt * 16) * 128 + (ks * 2 + a_ch) * 16));
                ldm4(ah[mt], stage + off);
                ldm4(alr[mt], stage + 16384 + off);
            }
            #pragma unroll
            for (int p = 0; p < 2; p++) {
                uint32_t off = swz((uint32_t)((b_row + p * 16) * 128 + (ks * 2 + b_ch) * 16));
                uint32_t rh[4], rl[4];
                ldm4(rh, stage + 32768 + off);
                ldm4(rl, stage + 49152 + off);
                bh[p * 2][0] = rh[0]; bh[p * 2][1] = rh[1];
                bh[p * 2 + 1][0] = rh[2]; bh[p * 2 + 1][1] = rh[3];
                bl[p * 2][0] = rl[0]; bl[p * 2][1] = rl[1];
                bl[p * 2 + 1][0] = rl[2]; bl[p * 2 + 1][1] = rl[3];
            }
            #pragma unroll
            for (int mt = 0; mt < 2; mt++)
                #pragma unroll
                for (int nt = 0; nt < 4; nt++) {
                    mma_bf16(acc[mt][nt], ah[mt], bh[nt]);
                    mma_bf16(acc[mt][nt], alr[mt], bh[nt]);
                    mma_bf16(acc[mt][nt], ah[mt], bl[nt]);
                }
        }
        __syncthreads();
    }

    #pragma unroll
    for (int mt = 0; mt < 2; mt++) {
        int r0 = bm + wm * 32 + mt * 16 + (lane >> 2);
        #pragma unroll
        for (int nt = 0; nt < 4; nt++) {
            int c0 = bn + wn * 32 + nt * 8 + (lane & 3) * 2;
            if (r0 < M)
                *(float2*)&C[(size_t)r0 * 256 + c0] = make_float2(acc[mt][nt][0], acc[mt][nt][1]);
            if (r0 + 8 < M)
                *(float2*)&C[(size_t)(r0 + 8) * 256 + c0] = make_float2(acc[mt][nt][2], acc[mt][nt][3]);
        }
    }

    int colbase = bn + wn * 32;
    if (colbase < el_cols) {
        #pragma unroll
        for (int mt = 0; mt < 2; mt++) {
            float p0 = 0.f, p1 = 0.f;
            #pragma unroll
            for (int nt = 0; nt < 4; nt++) {
                int gc = colbase + nt * 8 + (lane & 3) * 2;
                float a0 = al[gc], a1 = al[gc + 1];
                p0 += acc[mt][nt][0] * a0 + acc[mt][nt][1] * a1;
                p1 += acc[mt][nt][2] * a0 + acc[mt][nt][3] * a1;
            }
            p0 += __shfl_xor_sync(0xFFFFFFFFu, p0, 1);
            p0 += __shfl_xor_sync(0xFFFFFFFFu, p0, 2);
            p1 += __shfl_xor_sync(0xFFFFFFFFu, p1, 1);
            p1 += __shfl_xor_sync(0xFFFFFFFFu, p1, 2);
            if ((lane & 3) == 0) {
                int rl0 = wm * 32 + mt * 16 + (lane >> 2);
                if (el_pair) {
                    elbuf[wn][rl0] = p0;
                    elbuf[wn][rl0 + 8] = p1;
                } else {
                    int h = colbase >> hshift;
                    if (bm + rl0 < M) el[(bm + rl0) * 4 + h] = p0;
                    if (bm + rl0 + 8 < M) el[(bm + rl0 + 8) * 4 + h] = p1;
                }
            }
        }
    }
    if (el_pair) {
        __syncthreads();
        if (t < 256) {
            int r = t & 127;
            int pr = t >> 7;
            int gr = bm + r;
            if (gr < M) {
                float v = elbuf[pr * 2][r] + elbuf[pr * 2 + 1][r];
                int h = (bn >> 6) + pr;
                el[gr * 4 + h] = v;
            }
        }
    }
}

// ---------------- agg layer 1 (fused softmax, float2 gather, 128 thr) ----------------
// thread tid owns features {2*tid, 2*tid+1}; h = tid>>5. Duty lanes tid<64 load el float4.
__global__ void k_agg1(const int* __restrict__ rowptr, const int* __restrict__ csr_src,
                       const float* __restrict__ el, const float* __restrict__ er,
                       const float* __restrict__ fs, const float* __restrict__ hin,
                       __nv_bfloat16* __restrict__ hi, __nv_bfloat16* __restrict__ lo,
                       const float* __restrict__ ur2, float* __restrict__ er2) {
    int n = blockIdx.x;
    int tid = threadIdx.x;          // 128
    int h = tid >> 5;
    int beg = rowptr[n], end = rowptr[n + 1];
    __shared__ int ss[64];
    __shared__ float sw[4][64];
    __shared__ float red4[2][4];
    __shared__ float4 wsum[4];
    float4 erv = make_float4(0.f, 0.f, 0.f, 0.f);
    if (tid < 64) erv = *(const float4*)&er[n * 4];
    float acc0 = 0.f, acc1 = 0.f;
    float d0 = 0.f, d1 = 0.f, d2 = 0.f, d3 = 0.f;
    const float2* fs2 = (const float2*)fs;
    for (int base = beg; base < end; base += 64) {
        int m = min(64, end - base);
        __syncthreads();
        if (tid < m) ss[tid] = csr_src[base + tid];
        __syncthreads();
        if (tid < m) {
            int s = ss[tid];
            float4 e = *(const float4*)&el[s * 4];
            float w0 = __expf(lrelu(e.x + erv.x));
            float w1 = __expf(lrelu(e.y + erv.y));
            float w2 = __expf(lrelu(e.z + erv.z));
            float w3 = __expf(lrelu(e.w + erv.w));
            sw[0][tid] = w0; sw[1][tid] = w1; sw[2][tid] = w2; sw[3][tid] = w3;
            d0 += w0; d1 += w1; d2 += w2; d3 += w3;
        }
        __syncthreads();
        #pragma unroll 8
        for (int i = 0; i < m; i++) {
            float w = sw[h][i];
            float2 v = fs2[(size_t)ss[i] * 128 + tid];
            acc0 += w * v.x;
            acc1 += w * v.y;
        }
    }
    if (tid < 64) {
        #pragma unroll
        for (int o = 16; o; o >>= 1) {
            d0 += __shfl_xor_sync(0xFFFFFFFFu, d0, o);
            d1 += __shfl_xor_sync(0xFFFFFFFFu, d1, o);
            d2 += __shfl_xor_sync(0xFFFFFFFFu, d2, o);
            d3 += __shfl_xor_sync(0xFFFFFFFFu, d3, o);
        }
        if ((tid & 31) == 0) {
            red4[tid >> 5][0] = d0; red4[tid >> 5][1] = d1;
            red4[tid >> 5][2] = d2; red4[tid >> 5][3] = d3;
        }
    }
    __syncthreads();
    float den = red4[0][h] + red4[1][h];
    float inv = 1.f / den;
    float2 hv = ((const float2*)hin)[(size_t)n * 128 + tid];
    float v0 = acc0 * inv + hv.x;
    float v1 = acc1 * inv + hv.y;
    v0 = v0 > 0.f ? v0 : expm1f(v0);
    v1 = v1 > 0.f ? v1 : expm1f(v1);
    __nv_bfloat16 h0 = __float2bfloat16(v0);
    __nv_bfloat16 h1 = __float2bfloat16(v1);
    ((__nv_bfloat162*)hi)[(size_t)n * 128 + tid] = __nv_bfloat162(h0, h1);
    ((__nv_bfloat162*)lo)[(size_t)n * 128 + tid] =
        __nv_bfloat162(__float2bfloat16(v0 - __bfloat162float(h0)),
                       __float2bfloat16(v1 - __bfloat162float(h1)));
    const float4* ur4 = (const float4*)ur2;
    float4 u0 = ur4[tid * 2];
    float4 u1 = ur4[tid * 2 + 1];
    float4 p = make_float4(v0 * u0.x + v1 * u1.x, v0 * u0.y + v1 * u1.y,
                           v0 * u0.z + v1 * u1.z, v0 * u0.w + v1 * u1.w);
    #pragma unroll
    for (int o = 16; o; o >>= 1) {
        p.x += __shfl_xor_sync(0xFFFFFFFFu, p.x, o);
        p.y += __shfl_xor_sync(0xFFFFFFFFu, p.y, o);
        p.z += __shfl_xor_sync(0xFFFFFFFFu, p.z, o);
        p.w += __shfl_xor_sync(0xFFFFFFFFu, p.w, o);
    }
    if ((tid & 31) == 0) wsum[tid >> 5] = p;
    __syncthreads();
    if (tid == 0) {
        float4 s = wsum[0];
        #pragma unroll
        for (int i = 1; i < 4; i++) {
            s.x += wsum[i].x; s.y += wsum[i].y; s.z += wsum[i].z; s.w += wsum[i].w;
        }
        *(float4*)&er2[n * 4] = s;
    }
}

// ---------------- agg layer 2 (fused softmax) ----------------
__global__ void k_agg2(const int* __restrict__ rowptr, const int* __restrict__ csr_src,
                       const float* __restrict__ el, const float* __restrict__ er,
                       const float* __restrict__ c2, float* __restrict__ out) {
    int n = blockIdx.x;
    int tid = threadIdx.x;          // 128
    int h = tid >> 5;
    int wi = tid & 63;
    int whb = (tid >> 6) * 2;
    int beg = rowptr[n], end = rowptr[n + 1];
    __shared__ int ss[64];
    __shared__ float sw[4][64];
    __shared__ float red[4][2];
    __shared__ float sv[128];
    float er0 = er[n * 4 + whb], er1 = er[n * 4 + whb + 1];
    float acc = 0.f, den0 = 0.f, den1 = 0.f;
    for (int base = beg; base < end; base += 64) {
        int m = min(64, end - base);
        __syncthreads();
        if (tid < m) ss[tid] = csr_src[base + tid];
        __syncthreads();
        float w0 = 0.f, w1 = 0.f;
        if (wi < m) {
            int s = ss[wi];
            float2 ev = *(const float2*)&el[s * 4 + whb];
            w0 = __expf(lrelu(ev.x + er0));
            w1 = __expf(lrelu(ev.y + er1));
        }
        sw[whb][wi] = w0;
        sw[whb + 1][wi] = w1;
        den0 += w0; den1 += w1;
        __syncthreads();
        #pragma unroll 8
        for (int i = 0; i < m; i++)
            acc += sw[h][i] * c2[(size_t)ss[i] * 256 + tid];
    }
    #pragma unroll
    for (int o = 16; o; o >>= 1) {
        den0 += __shfl_xor_sync(0xFFFFFFFFu, den0, o);
        den1 += __shfl_xor_sync(0xFFFFFFFFu, den1, o);
    }
    if ((tid & 31) == 0) { red[tid >> 5][0] = den0; red[tid >> 5][1] = den1; }
    __syncthreads();
    float den = red[(h >> 1) * 2][h & 1] + red[(h >> 1) * 2 + 1][h & 1];
    sv[tid] = acc / den + c2[(size_t)n * 256 + 128 + tid];
    __syncthreads();
    if (tid < 32)
        out[(size_t)n * 32 + tid] =
            (sv[tid] + sv[32 + tid] + sv[64 + tid] + sv[96 + tid]) * 0.25f;
}

// ---------------- launch ----------------
extern "C" void kernel_launch(void* const* d_in, const int* in_sizes, int n_in,
                              void* d_out, int out_size) {
    const float* h      = (const float*)d_in[0];
    const int*   src    = (const int*)d_in[1];
    const int*   dst    = (const int*)d_in[2];
    const float* W1_src = (const float*)d_in[3];
    const float* W1_dst = (const float*)d_in[4];
    const float* al1    = (const float*)d_in[5];
    const float* ar1    = (const float*)d_in[6];
    const float* W2_src = (const float*)d_in[7];
    const float* W2_dst = (const float*)d_in[8];
    const float* al2    = (const float*)d_in[9];
    const float* ar2    = (const float*)d_in[10];
    const float* Wres2  = (const float*)d_in[11];
    float* out = (float*)d_out;

    int N = in_sizes[0] / 256;
    int E = in_sizes[1];

    float *fs1, *c2, *el1, *el2, *er, *ur1, *ur2;
    int *cnt, *cursor, *rowptr, *partial, *csr_src;
    __nv_bfloat16 *Ahi, *Alo, *B1h, *B1l, *BCh, *BCl;
    cudaGetSymbolAddress((void**)&fs1, g_fs1);
    cudaGetSymbolAddress((void**)&c2, g_c2);
    cudaGetSymbolAddress((void**)&el1, g_el1);
    cudaGetSymbolAddress((void**)&el2, g_el2);
    cudaGetSymbolAddress((void**)&er, g_er);
    cudaGetSymbolAddress((void**)&ur1, g_ur1);
    cudaGetSymbolAddress((void**)&ur2, g_ur2);
    cudaGetSymbolAddress((void**)&cnt, g_cnt);
    cudaGetSymbolAddress((void**)&cursor, g_cursor);
    cudaGetSymbolAddress((void**)&rowptr, g_rowptr);
    cudaGetSymbolAddress((void**)&partial, g_partial);
    cudaGetSymbolAddress((void**)&csr_src, g_csr_src);
    cudaGetSymbolAddress((void**)&Ahi, g_Ahi);
    cudaGetSymbolAddress((void**)&Alo, g_Alo);
    cudaGetSymbolAddress((void**)&B1h, g_B1hi);
    cudaGetSymbolAddress((void**)&B1l, g_B1lo);
    cudaGetSymbolAddress((void**)&BCh, g_BChi);
    cudaGetSymbolAddress((void**)&BCl, g_BClo);

    static cudaStream_t s1 = nullptr;
    static cudaEvent_t ev0 = nullptr, ev1 = nullptr;
    if (!s1) {
        cudaStreamCreateWithFlags(&s1, cudaStreamNonBlocking);
        cudaEventCreateWithFlags(&ev0, cudaEventDisableTiming);
        cudaEventCreateWithFlags(&ev1, cudaEventDisableTiming);
        cudaFuncSetAttribute(k_mma, cudaFuncAttributeMaxDynamicSharedMemorySize, GEMM_SMEM);
    }

    int gE = (E + 255) / 256;
    int gN = (N + 255) / 256;
    int nScanB = (N + 1023) / 1024;
    int gemmM = (N + 127) / 128;

    // clear (cnt/cursor for CSR)
    k_clear<<<gN, 256>>>(cnt, cursor, N);
    cudaEventRecord(ev0, 0);

    // ---- side stream s1: CSR build ----
    cudaStreamWaitEvent(s1, ev0, 0);
    k_count<<<gE, 256, 0, s1>>>(dst, cnt, E);
    k_scan1<<<nScanB, 1024, 0, s1>>>(cnt, rowptr, partial, N);
    k_scan3<<<(N + 255) / 256, 256, 0, s1>>>(rowptr, partial, N, E);
    k_fill<<<gE, 256, 0, s1>>>(src, dst, rowptr, cursor, csr_src, E);
    cudaEventRecord(ev1, s1);

    // ---- main stream: weight prep + convert + GEMM L1 ----
    k_prep<<<dim3(256, 4), 256>>>(W1_src, W2_src, Wres2, W1_dst, ar1, W2_dst, ar2,
                                  B1h, B1l, BCh, BCl, ur1, ur2);
    k_convA_er<<<(N + 7) / 8, 256>>>(h, Ahi, Alo, ur1, er, N);
    k_mma<<<dim3(gemmM, 2), 512, GEMM_SMEM>>>(Ahi, Alo, B1h, B1l, fs1, N,
                                              el1, al1, 6, 256, 1);

    // join CSR branch, then fused softmax+aggregation (writes bf16 h1 into Ahi/Alo)
    cudaStreamWaitEvent(0, ev1, 0);
    k_agg1<<<N, 128>>>(rowptr, csr_src, el1, er, fs1, h, Ahi, Alo, ur2, er);

    // ---- layer 2 ----
    k_mma<<<dim3(gemmM, 2), 512, GEMM_SMEM>>>(Ahi, Alo, BCh, BCl, c2, N,
                                              el2, al2, 5, 128, 0);
    k_agg2<<<N, 128>>>(rowptr, csr_src, el2, er, c2, out);
}